// round 7
// baseline (speedup 1.0000x reference)
#include <cuda_runtime.h>
#include <stdint.h>

#define TT 3
#define FF 17
#define NN 8
#define DT 0.2f
#define EPS 1e-8f

// PWL representation of the three hot MLPs (an=0, rn=1, rb=2):
//   f(x) = A[k]*x + C[k],  k = #{ j : t_j <= x } over sorted thresholds t[0..31]
__device__ float g_t[3][32];
__device__ float g_A[3][33];
__device__ float g_C[3][33];
__device__ float g_attr_dl[8];

// ---------------------------------------------------------------------------
// Setup: 128 threads. Warps 0-2 build the three PWL tables IN PARALLEL using
// warp-parallel suffix scans. Warp 3 (lanes 0-7) computes the dl-MLP constants
// (dur depends only on ego batch row 1).
// ---------------------------------------------------------------------------
__global__ void sfm_precompute(const float* __restrict__ ego,
    const float* __restrict__ an_wi, const float* __restrict__ an_bi,
    const float* __restrict__ an_wo, const float* __restrict__ an_bo,
    const float* __restrict__ rn_wi, const float* __restrict__ rn_bi,
    const float* __restrict__ rn_wo, const float* __restrict__ rn_bo,
    const float* __restrict__ rb_wi, const float* __restrict__ rb_bi,
    const float* __restrict__ rb_wo, const float* __restrict__ rb_bo,
    const float* __restrict__ dl_wi, const float* __restrict__ dl_bi,
    const float* __restrict__ dl_wo, const float* __restrict__ dl_bo)
{
    __shared__ float sh[3][3][32];
    int tid = threadIdx.x;
    int w = tid >> 5, lane = tid & 31;
    const unsigned FULL = 0xffffffffu;
    const float PINF = __int_as_float(0x7f800000);

    if (w < 3) {
        const float* wi = (w == 0) ? an_wi : (w == 1) ? rn_wi : rb_wi;
        const float* bi = (w == 0) ? an_bi : (w == 1) ? rn_bi : rb_bi;
        const float* wo = (w == 0) ? an_wo : (w == 1) ? rn_wo : rb_wo;
        const float* bo = (w == 0) ? an_bo : (w == 1) ? rn_bo : rb_bo;

        float wiv = wi[lane], biv = bi[lane], wov = wo[lane];
        float bov = bo[0];
        // relu(-(wi*x+bi)) active iff x < t  (wi uniform >= 0)
        float t, slope, icept;
        if (wiv > 0.f) {
            t = -biv / wiv;
            slope = -wov * wiv;
            icept = -wov * biv;
        } else if (biv < 0.f) {       // always active, constant -bi
            t = PINF; slope = 0.f; icept = -wov * biv;
        } else {                      // never active
            t = -PINF; slope = 0.f; icept = 0.f;
        }

        // rank-sort ascending (ties by lane) via shuffles
        int rank = 0;
#pragma unroll
        for (int i = 0; i < 32; i++) {
            float ti = __shfl_sync(FULL, t, i);
            rank += (ti < t) || (ti == t && i < lane);
        }
        sh[w][0][rank] = t; sh[w][1][rank] = slope; sh[w][2][rank] = icept;
        __syncwarp();
        float ts = sh[w][0][lane];
        float A  = sh[w][1][lane];
        float C  = sh[w][2][lane];

        // inclusive suffix scan: A[k] = sum_{j>=k} slope[j], same for C
#pragma unroll
        for (int off = 1; off < 32; off <<= 1) {
            float a2 = __shfl_down_sync(FULL, A, off);
            float c2 = __shfl_down_sync(FULL, C, off);
            if (lane + off < 32) { A += a2; C += c2; }
        }
        C += bov;

        g_t[w][lane] = ts;
        g_A[w][lane] = A;
        g_C[w][lane] = C;
        if (lane == 0) { g_A[w][32] = 0.f; g_C[w][32] = bov; }
    } else if (lane < 8) {
        // dl MLP on dur[n] (depends only on ego batch row 1)
        const float* e1 = ego + (size_t)1 * TT * FF;
        float id = e1[(TT - 1) * FF + 8 + lane];
        float dur = 0.f;
#pragma unroll
        for (int t = 0; t < TT; t++) {
            bool found = false;
#pragma unroll
            for (int k = 0; k < 8; k++)
                found = found || (e1[t * FF + 8 + k] == id);
            dur += found ? 1.f : 0.f;
        }
        float acc = dl_bo[0];
#pragma unroll
        for (int j = 0; j < 32; j++) {
            float h = fmaxf(-fmaf(dl_wi[j], dur, dl_bi[j]), 0.f);
            acc = fmaf(dl_wo[j], h, acc);
        }
        g_attr_dl[lane] = acc;
    }
}

// Branchless count of sorted thresholds <= x (k in [0,32]), then 1 FMA.
__device__ __forceinline__ float pwl_eval(const float* __restrict__ t,
                                          const float* __restrict__ A,
                                          const float* __restrict__ C,
                                          float x)
{
    int k = 0;
    if (t[15]    <= x) k  = 16;
    if (t[k + 7] <= x) k += 8;
    if (t[k + 3] <= x) k += 4;
    if (t[k + 1] <= x) k += 2;
    if (t[k]     <= x) k += 1;   // k in [0,31]
    if (t[31]    <= x) k += 1;   // all <= x  => k = 32
    return fmaf(A[k], x, C[k]);
}

// ---------------------------------------------------------------------------
// Main kernel: one thread per agent, 256 agents per block.
// The neighbor block (256 agents x 136 floats, contiguous in gmem) is staged
// into smem with FULLY COALESCED scalar loads (1 L1 wavefront per warp-LDG,
// ~9x fewer wavefronts than scattered per-thread loads), keeping only the 4
// needed fields per neighbor. smem layout stride 33 -> conflict-free LDS.
// All global accesses remain scalar floats (vector loads faulted in R2-R3).
// ---------------------------------------------------------------------------
#define AG 256                 // agents per block
#define ROW 136                // floats per agent in nei (8*17)
#define SST 33                 // smem stride per agent (32 used + 1 pad)

__global__ void __launch_bounds__(256) sfm_main(
    const float* __restrict__ ego, const float* __restrict__ nei,
    const float* __restrict__ border, const float* __restrict__ adp,
    const float* __restrict__ eff_angle,
    float* __restrict__ out, int n_batch)
{
    __shared__ float st[3][32];
    __shared__ float sA[3][33];
    __shared__ float sC[3][33];
    __shared__ float sdl[8];
    __shared__ float snei[AG * SST];   // 33 KB

    int tid = threadIdx.x;
    for (int i = tid; i < 96; i += 256) ((float*)st)[i] = ((const float*)g_t)[i];
    for (int i = tid; i < 99; i += 256) ((float*)sA)[i] = ((const float*)g_A)[i];
    for (int i = tid; i < 99; i += 256) ((float*)sC)[i] = ((const float*)g_C)[i];
    if (tid < 8) sdl[tid] = g_attr_dl[tid];

    int base = blockIdx.x * AG;
    int b = base + tid;
    bool full_tile = (base + AG <= n_batch);

    if (full_tile) {
        // ---- coalesced staging of the block's entire nei region ----
        const float* src = nei + (size_t)base * ROW;
#pragma unroll 8
        for (int r = 0; r < ROW; r++) {
            int idx = r * 256 + tid;           // 0 .. 256*136-1
            float v = src[idx];
            int agent = idx / ROW;
            int f     = idx - agent * ROW;     // 0..135
            int n     = f / FF;
            int c     = f - n * FF - 2;        // want 0..3 (features 2..5)
            if ((unsigned)c < 4u)
                snei[agent * SST + n * 4 + c] = v;
        }
    }
    __syncthreads();

    if (b >= n_batch) return;

    // ego_last fields 0..5 (scalar loads)
    const float* eg = ego + (size_t)b * (TT * FF) + (TT - 1) * FF;
    float g0 = eg[0], g1 = eg[1], g2 = eg[2], g3 = eg[3], g4 = eg[4], g5 = eg[5];

    // heading + angle threshold (division-free clamp: |dot| > thr * ||f||)
    float einv = rsqrtf(g4 * g4 + g5 * g5);
    float ex = g4 * einv, ey = g5 * einv;
    float na = fmaxf(sqrtf(ex * ex + ey * ey), EPS);
    float thr = eff_angle[0] * na;

    float ax = 0.f, ay = 0.f;

    // f_dest: v34 = (g3, g4); dv = (|v34|, 0)
    {
        float nv = sqrtf(g3 * g3 + g4 * g4);
        float p0 = adp[0], p1 = adp[1];
        float fx = (p1 * nv - g3) / p0;
        float fy = (0.f - g4) / p0;
        float dot = ex * fx + ey * fy;
        float nbn = fmaxf(sqrtf(fx * fx + fy * fy), EPS);
        bool keep = fabsf(dot) > thr * nbn;
        ax += keep ? fx : 0.f;
        ay += keep ? fy : 0.f;
    }

    // neighbors: attr + repu share direction r, so one keep-test covers both
    const float* nb = nei + (size_t)b * (NN * FF);   // fallback path only
    const float* sn = snei + tid * SST;
#pragma unroll
    for (int n = 0; n < 8; n++) {
        float a2, a3, a4, a5;
        if (full_tile) {
            a2 = sn[n * 4 + 0]; a3 = sn[n * 4 + 1];
            a4 = sn[n * 4 + 2]; a5 = sn[n * 4 + 3];
        } else {
            const float* p = nb + n * FF;
            a2 = p[2]; a3 = p[3]; a4 = p[4]; a5 = p[5];
        }

        bool mx = (a2 == 0.f), my = (a3 == 0.f);
        float rx = a2 - g2, ry = a3 - g3;
        float rnm = sqrtf(rx * rx + ry * ry);
        float vx = a4 * DT, vy = a5 * DT;
        float px = rx + vx, py = ry + vy;
        float bbv = sqrtf(rnm + px * px + py * py - vx * vx - vy * vy) * 0.5f;

        float fa = pwl_eval(st[0], sA[0], sC[0], rnm);   // an MLP on r_norm
        float fr = pwl_eval(st[1], sA[1], sC[1], bbv);   // rn MLP on b
        float s = (fa * sdl[n] + fr) / rnm;              // combined scalar factor

        float fxb = mx ? 0.f : rx;
        float fyb = my ? 0.f : ry;
        float dot = ex * fxb + ey * fyb;
        float nbn = sqrtf(fxb * fxb + fyb * fyb);
        bool keep = fabsf(dot) > thr * nbn;
        ax += keep ? s * fxb : 0.f;
        ay += keep ? s * fyb : 0.f;
    }

    // f_bor: y-only vectors, magnitude rb(|rbv|), direction sign(rbv)
    {
        float rbv0 = g3 - border[0];
        float rbv1 = g3 - border[3];
        float rbn0 = fabsf(rbv0), rbn1 = fabsf(rbv1);

        float m0 = pwl_eval(st[2], sA[2], sC[2], rbn0);
        float m1 = pwl_eval(st[2], sA[2], sC[2], rbn1);

        float fy0 = m0 * (rbv0 / rbn0);
        float nbn0 = fmaxf(fabsf(fy0), EPS);
        if (fabsf(ey * fy0) > thr * nbn0) ay += fy0;

        float fy1 = m1 * (rbv1 / rbn1);
        float nbn1 = fmaxf(fabsf(fy1), EPS);
        if (fabsf(ey * fy1) > thr * nbn1) ay += fy1;
    }

    float vxo = g2 + ax * DT;
    float vyo = g3 + ay * DT;
    float sx = g0 + vxo * DT;
    float sy = g1 + vyo * DT;

    float* o = out + (size_t)b * 6;     // scalar stores only
    o[0] = sx; o[1] = sy;
    o[2] = vxo; o[3] = vyo;
    o[4] = ax;  o[5] = ay;
}

extern "C" void kernel_launch(void* const* d_in, const int* in_sizes, int n_in,
                              void* d_out, int out_size)
{
    const float* ego    = (const float*)d_in[0];
    const float* nei    = (const float*)d_in[1];
    const float* border = (const float*)d_in[2];
    const float* adp    = (const float*)d_in[3];
    const float* eff    = (const float*)d_in[4];
    const float* an_wi  = (const float*)d_in[5];
    const float* an_bi  = (const float*)d_in[6];
    const float* an_wo  = (const float*)d_in[7];
    const float* an_bo  = (const float*)d_in[8];
    const float* rn_wi  = (const float*)d_in[9];
    const float* rn_bi  = (const float*)d_in[10];
    const float* rn_wo  = (const float*)d_in[11];
    const float* rn_bo  = (const float*)d_in[12];
    const float* rb_wi  = (const float*)d_in[13];
    const float* rb_bi  = (const float*)d_in[14];
    const float* rb_wo  = (const float*)d_in[15];
    const float* rb_bo  = (const float*)d_in[16];
    const float* dl_wi  = (const float*)d_in[17];
    const float* dl_bi  = (const float*)d_in[18];
    const float* dl_wo  = (const float*)d_in[19];
    const float* dl_bo  = (const float*)d_in[20];
    float* out = (float*)d_out;

    int n_batch = in_sizes[0] / (TT * FF);

    sfm_precompute<<<1, 128>>>(ego,
                               an_wi, an_bi, an_wo, an_bo,
                               rn_wi, rn_bi, rn_wo, rn_bo,
                               rb_wi, rb_bi, rb_wo, rb_bo,
                               dl_wi, dl_bi, dl_wo, dl_bo);

    int blocks = (n_batch + AG - 1) / AG;
    sfm_main<<<blocks, 256>>>(ego, nei, border, adp, eff, out, n_batch);
}

// round 8
// speedup vs baseline: 1.5523x; 1.5523x over previous
#include <cuda_runtime.h>
#include <stdint.h>

#define TT 3
#define FF 17
#define NN 8
#define DT 0.2f
#define EPS 1e-8f

// PWL representation of the three hot MLPs (an=0, rn=1, rb=2):
//   f(x) = A[k]*x + C[k],  k = #{ j : t_j <= x } over sorted thresholds t[0..31]
__device__ float g_t[3][32];
__device__ float g_A[3][33];
__device__ float g_C[3][33];
__device__ float g_attr_dl[8];

// ---------------------------------------------------------------------------
// Setup: 128 threads. Warps 0-2 build the three PWL tables IN PARALLEL using
// warp-parallel suffix scans. Warp 3 (lanes 0-7) computes the dl-MLP constants
// (dur depends only on ego batch row 1).
// ---------------------------------------------------------------------------
__global__ void sfm_precompute(const float* __restrict__ ego,
    const float* __restrict__ an_wi, const float* __restrict__ an_bi,
    const float* __restrict__ an_wo, const float* __restrict__ an_bo,
    const float* __restrict__ rn_wi, const float* __restrict__ rn_bi,
    const float* __restrict__ rn_wo, const float* __restrict__ rn_bo,
    const float* __restrict__ rb_wi, const float* __restrict__ rb_bi,
    const float* __restrict__ rb_wo, const float* __restrict__ rb_bo,
    const float* __restrict__ dl_wi, const float* __restrict__ dl_bi,
    const float* __restrict__ dl_wo, const float* __restrict__ dl_bo)
{
    __shared__ float sh[3][3][32];
    int tid = threadIdx.x;
    int w = tid >> 5, lane = tid & 31;
    const unsigned FULL = 0xffffffffu;
    const float PINF = __int_as_float(0x7f800000);

    if (w < 3) {
        const float* wi = (w == 0) ? an_wi : (w == 1) ? rn_wi : rb_wi;
        const float* bi = (w == 0) ? an_bi : (w == 1) ? rn_bi : rb_bi;
        const float* wo = (w == 0) ? an_wo : (w == 1) ? rn_wo : rb_wo;
        const float* bo = (w == 0) ? an_bo : (w == 1) ? rn_bo : rb_bo;

        float wiv = wi[lane], biv = bi[lane], wov = wo[lane];
        float bov = bo[0];
        // relu(-(wi*x+bi)) active iff x < t  (wi uniform >= 0)
        float t, slope, icept;
        if (wiv > 0.f) {
            t = -biv / wiv;
            slope = -wov * wiv;
            icept = -wov * biv;
        } else if (biv < 0.f) {       // always active, constant -bi
            t = PINF; slope = 0.f; icept = -wov * biv;
        } else {                      // never active
            t = -PINF; slope = 0.f; icept = 0.f;
        }

        // rank-sort ascending (ties by lane) via shuffles
        int rank = 0;
#pragma unroll
        for (int i = 0; i < 32; i++) {
            float ti = __shfl_sync(FULL, t, i);
            rank += (ti < t) || (ti == t && i < lane);
        }
        sh[w][0][rank] = t; sh[w][1][rank] = slope; sh[w][2][rank] = icept;
        __syncwarp();
        float ts = sh[w][0][lane];
        float A  = sh[w][1][lane];
        float C  = sh[w][2][lane];

        // inclusive suffix scan: A[k] = sum_{j>=k} slope[j], same for C
#pragma unroll
        for (int off = 1; off < 32; off <<= 1) {
            float a2 = __shfl_down_sync(FULL, A, off);
            float c2 = __shfl_down_sync(FULL, C, off);
            if (lane + off < 32) { A += a2; C += c2; }
        }
        C += bov;

        g_t[w][lane] = ts;
        g_A[w][lane] = A;
        g_C[w][lane] = C;
        if (lane == 0) { g_A[w][32] = 0.f; g_C[w][32] = bov; }
    } else if (lane < 8) {
        // dl MLP on dur[n] (depends only on ego batch row 1)
        const float* e1 = ego + (size_t)1 * TT * FF;
        float id = e1[(TT - 1) * FF + 8 + lane];
        float dur = 0.f;
#pragma unroll
        for (int t = 0; t < TT; t++) {
            bool found = false;
#pragma unroll
            for (int k = 0; k < 8; k++)
                found = found || (e1[t * FF + 8 + k] == id);
            dur += found ? 1.f : 0.f;
        }
        float acc = dl_bo[0];
#pragma unroll
        for (int j = 0; j < 32; j++) {
            float h = fmaxf(-fmaf(dl_wi[j], dur, dl_bi[j]), 0.f);
            acc = fmaf(dl_wo[j], h, acc);
        }
        g_attr_dl[lane] = acc;
    }
}

// Branchless count of sorted thresholds <= x (k in [0,32]), then 1 FMA.
__device__ __forceinline__ float pwl_eval(const float* __restrict__ t,
                                          const float* __restrict__ A,
                                          const float* __restrict__ C,
                                          float x)
{
    int k = 0;
    if (t[15]    <= x) k  = 16;
    if (t[k + 7] <= x) k += 8;
    if (t[k + 3] <= x) k += 4;
    if (t[k + 1] <= x) k += 2;
    if (t[k]     <= x) k += 1;   // k in [0,31]
    if (t[31]    <= x) k += 1;   // all <= x  => k = 32
    return fmaf(A[k], x, C[k]);
}

// ---------------------------------------------------------------------------
// Main kernel: one thread per agent, 256 agents per block.
// Staging uses LANE-CONSTANT gather offsets (no div/mod at runtime):
//  - nei: one warp-load fetches ONE agent's 32 needed floats
//         (lane l -> neighbor l>>2, field 2+(l&3)); spans 488B ~= 5 wavefronts
//         per agent vs 32 wavefronts/load for scattered per-thread access.
//  - ego: one warp-load fetches 5 agents x 6 fields (lanes 0-29).
// All global accesses remain scalar floats (vector loads faulted in R2-R3).
// ---------------------------------------------------------------------------
#define AG 256                 // agents per block
#define NROW 136               // floats per agent in nei (8*17)
#define EROW 51                // floats per agent in ego (3*17)
#define SST 33                 // snei stride per agent (32 used + 1 pad)
#define EST 7                  // sego stride per agent (6 used + 1 pad)

__global__ void __launch_bounds__(256) sfm_main(
    const float* __restrict__ ego, const float* __restrict__ nei,
    const float* __restrict__ border, const float* __restrict__ adp,
    const float* __restrict__ eff_angle,
    float* __restrict__ out, int n_batch)
{
    __shared__ float st[3][32];
    __shared__ float sA[3][33];
    __shared__ float sC[3][33];
    __shared__ float sdl[8];
    __shared__ float snei[AG * SST];   // ~33 KB
    __shared__ float sego[AG * EST];   // ~7 KB

    int tid  = threadIdx.x;
    int warp = tid >> 5, lane = tid & 31;

    for (int i = tid; i < 96; i += 256) ((float*)st)[i] = ((const float*)g_t)[i];
    for (int i = tid; i < 99; i += 256) ((float*)sA)[i] = ((const float*)g_A)[i];
    for (int i = tid; i < 99; i += 256) ((float*)sC)[i] = ((const float*)g_C)[i];
    if (tid < 8) sdl[tid] = g_attr_dl[tid];

    int base = blockIdx.x * AG;
    int b = base + tid;
    bool full_tile = (base + AG <= n_batch);

    if (full_tile) {
        // ---- nei staging: warp w handles agents [w*32, w*32+32) ----
        // lane-constant gather offset within an agent's nei row
        int nOff = (lane >> 2) * FF + 2 + (lane & 3);     // neighbor l/4, field 2+l%4
        const float* nsrc = nei + (size_t)(base + warp * 32) * NROW + nOff;
        float* ndst = snei + (warp * 32) * SST + lane;
#pragma unroll 8
        for (int a = 0; a < 32; a++) {
            ndst[a * SST] = nsrc[(size_t)a * NROW];
        }

        // ---- ego staging: 5 agents x 6 fields per warp-load (lanes 0-29) ----
        int ea = lane / 6;            // 0..5 (5 invalid for lane 30,31 -> ea=5)
        int ef = lane - ea * 6;       // 0..5
        if (lane < 30) {
            const float* esrc = ego + (size_t)(base + warp * 32 + ea) * EROW
                                    + (TT - 1) * FF + ef;
            float* edst = sego + (warp * 32 + ea) * EST + ef;
#pragma unroll
            for (int i = 0; i < 7; i++) {          // agents ea, ea+5, ..., ea+30
                if (ea + i * 5 < 32)
                    edst[i * 5 * EST] = esrc[(size_t)i * 5 * EROW];
            }
        }
    }
    __syncthreads();

    if (b >= n_batch) return;

    // ego_last fields 0..5
    float g0, g1, g2, g3, g4, g5;
    if (full_tile) {
        const float* se = sego + tid * EST;
        g0 = se[0]; g1 = se[1]; g2 = se[2]; g3 = se[3]; g4 = se[4]; g5 = se[5];
    } else {
        const float* eg = ego + (size_t)b * EROW + (TT - 1) * FF;
        g0 = eg[0]; g1 = eg[1]; g2 = eg[2]; g3 = eg[3]; g4 = eg[4]; g5 = eg[5];
    }

    // heading + angle threshold (division-free clamp: |dot| > thr * ||f||)
    float einv = rsqrtf(g4 * g4 + g5 * g5);
    float ex = g4 * einv, ey = g5 * einv;
    float na = fmaxf(sqrtf(ex * ex + ey * ey), EPS);
    float thr = eff_angle[0] * na;

    float ax = 0.f, ay = 0.f;

    // f_dest: v34 = (g3, g4); dv = (|v34|, 0)
    {
        float nv = sqrtf(g3 * g3 + g4 * g4);
        float p0 = adp[0], p1 = adp[1];
        float fx = (p1 * nv - g3) / p0;
        float fy = (0.f - g4) / p0;
        float dot = ex * fx + ey * fy;
        float nbn = fmaxf(sqrtf(fx * fx + fy * fy), EPS);
        bool keep = fabsf(dot) > thr * nbn;
        ax += keep ? fx : 0.f;
        ay += keep ? fy : 0.f;
    }

    // neighbors: attr + repu share direction r, so one keep-test covers both
    const float* nb = nei + (size_t)b * NROW;       // fallback path only
    const float* sn = snei + tid * SST;
#pragma unroll
    for (int n = 0; n < 8; n++) {
        float a2, a3, a4, a5;
        if (full_tile) {
            a2 = sn[n * 4 + 0]; a3 = sn[n * 4 + 1];
            a4 = sn[n * 4 + 2]; a5 = sn[n * 4 + 3];
        } else {
            const float* p = nb + n * FF;
            a2 = p[2]; a3 = p[3]; a4 = p[4]; a5 = p[5];
        }

        bool mx = (a2 == 0.f), my = (a3 == 0.f);
        float rx = a2 - g2, ry = a3 - g3;
        float rnm = sqrtf(rx * rx + ry * ry);
        float vx = a4 * DT, vy = a5 * DT;
        float px = rx + vx, py = ry + vy;
        float bbv = sqrtf(rnm + px * px + py * py - vx * vx - vy * vy) * 0.5f;

        float fa = pwl_eval(st[0], sA[0], sC[0], rnm);   // an MLP on r_norm
        float fr = pwl_eval(st[1], sA[1], sC[1], bbv);   // rn MLP on b
        float s = (fa * sdl[n] + fr) / rnm;              // combined scalar factor

        float fxb = mx ? 0.f : rx;
        float fyb = my ? 0.f : ry;
        float dot = ex * fxb + ey * fyb;
        float nbn = sqrtf(fxb * fxb + fyb * fyb);
        bool keep = fabsf(dot) > thr * nbn;
        ax += keep ? s * fxb : 0.f;
        ay += keep ? s * fyb : 0.f;
    }

    // f_bor: y-only vectors, magnitude rb(|rbv|), direction sign(rbv)
    {
        float rbv0 = g3 - border[0];
        float rbv1 = g3 - border[3];
        float rbn0 = fabsf(rbv0), rbn1 = fabsf(rbv1);

        float m0 = pwl_eval(st[2], sA[2], sC[2], rbn0);
        float m1 = pwl_eval(st[2], sA[2], sC[2], rbn1);

        float fy0 = m0 * (rbv0 / rbn0);
        float nbn0 = fmaxf(fabsf(fy0), EPS);
        if (fabsf(ey * fy0) > thr * nbn0) ay += fy0;

        float fy1 = m1 * (rbv1 / rbn1);
        float nbn1 = fmaxf(fabsf(fy1), EPS);
        if (fabsf(ey * fy1) > thr * nbn1) ay += fy1;
    }

    float vxo = g2 + ax * DT;
    float vyo = g3 + ay * DT;
    float sx = g0 + vxo * DT;
    float sy = g1 + vyo * DT;

    float* o = out + (size_t)b * 6;     // scalar stores only
    o[0] = sx; o[1] = sy;
    o[2] = vxo; o[3] = vyo;
    o[4] = ax;  o[5] = ay;
}

extern "C" void kernel_launch(void* const* d_in, const int* in_sizes, int n_in,
                              void* d_out, int out_size)
{
    const float* ego    = (const float*)d_in[0];
    const float* nei    = (const float*)d_in[1];
    const float* border = (const float*)d_in[2];
    const float* adp    = (const float*)d_in[3];
    const float* eff    = (const float*)d_in[4];
    const float* an_wi  = (const float*)d_in[5];
    const float* an_bi  = (const float*)d_in[6];
    const float* an_wo  = (const float*)d_in[7];
    const float* an_bo  = (const float*)d_in[8];
    const float* rn_wi  = (const float*)d_in[9];
    const float* rn_bi  = (const float*)d_in[10];
    const float* rn_wo  = (const float*)d_in[11];
    const float* rn_bo  = (const float*)d_in[12];
    const float* rb_wi  = (const float*)d_in[13];
    const float* rb_bi  = (const float*)d_in[14];
    const float* rb_wo  = (const float*)d_in[15];
    const float* rb_bo  = (const float*)d_in[16];
    const float* dl_wi  = (const float*)d_in[17];
    const float* dl_bi  = (const float*)d_in[18];
    const float* dl_wo  = (const float*)d_in[19];
    const float* dl_bo  = (const float*)d_in[20];
    float* out = (float*)d_out;

    int n_batch = in_sizes[0] / (TT * FF);

    sfm_precompute<<<1, 128>>>(ego,
                               an_wi, an_bi, an_wo, an_bo,
                               rn_wi, rn_bi, rn_wo, rn_bo,
                               rb_wi, rb_bi, rb_wo, rb_bo,
                               dl_wi, dl_bi, dl_wo, dl_bo);

    int blocks = (n_batch + AG - 1) / AG;
    sfm_main<<<blocks, 256>>>(ego, nei, border, adp, eff, out, n_batch);
}